// round 12
// baseline (speedup 1.0000x reference)
#include <cuda_runtime.h>
#include <cuda_fp16.h>
#include <cstdint>

// Problem constants (match reference)
#define NN 100000
#define EE 3200000
#define DD 256

// ---------------- scratch (device globals; no allocations allowed) ------------
__device__ __half2 g_hbuf_a[(size_t)NN * 128];   // support (fp16)     51.2 MB
__device__ __half2 g_hbuf_b[(size_t)NN * 128];   // h1 fp16            51.2 MB
__device__ __half2 g_hbuf_c[(size_t)NN * 128];   // h2 fp16            51.2 MB
__device__ unsigned char g_q1[(size_t)NN * 256]; // h1 int8            25.6 MB
__device__ unsigned char g_q2[(size_t)NN * 256]; // h2 int8            25.6 MB
__device__ float   g_s1[NN];                     // h1 row scales
__device__ float   g_s2[NN];                     // h2 row scales
__device__ __half2 g_Ah[(size_t)NN * 128];       // x hi split         51.2 MB
__device__ __half2 g_Al[(size_t)NN * 128];       // x lo split         51.2 MB
__device__ __half2 g_Bh2[256 * 128];             // W^T hi  [N,K]
__device__ __half2 g_Bl2[256 * 128];             // W^T lo  [N,K]
__device__ int     g_row_ptr[NN + 1];
__device__ int     g_cursor[NN + 1];             // doubles as counts
__device__ int2    g_csr[EE];                    // {col, weight-bits} interleaved

// ---------------- CSR build ---------------------------------------------------
__global__ void zero_counts_kernel(int n) {
    int i = blockIdx.x * blockDim.x + threadIdx.x;
    if (i < n) g_cursor[i] = 0;
}

__global__ void hist_kernel(const int* __restrict__ er, int E) {
    int i = blockIdx.x * blockDim.x + threadIdx.x;
    if (i < E) atomicAdd(&g_cursor[er[i]], 1);
}

__global__ void scan_kernel(int n, int E) {
    const int T = 1024;
    int tid = threadIdx.x;
    int per = (n + T - 1) / T;
    int beg = tid * per;
    int end = beg + per; if (end > n) end = n;

    int sum = 0;
    for (int j = beg; j < end; j++) sum += g_cursor[j];

    __shared__ int s[T];
    s[tid] = sum;
    __syncthreads();
    for (int off = 1; off < T; off <<= 1) {
        int v = (tid >= off) ? s[tid - off] : 0;
        __syncthreads();
        s[tid] += v;
        __syncthreads();
    }
    int run = s[tid] - sum;
    for (int j = beg; j < end; j++) {
        int c = g_cursor[j];
        g_row_ptr[j] = run;
        g_cursor[j]  = run;
        run += c;
    }
    if (tid == 0) g_row_ptr[n] = s[T - 1];
}

__global__ void scatter_kernel(const int* __restrict__ er, const int* __restrict__ ec,
                               const float* __restrict__ ew, int E) {
    int i = blockIdx.x * blockDim.x + threadIdx.x;
    if (i < E) {
        int r = er[i];
        int p = atomicAdd(&g_cursor[r], 1);
        g_csr[p] = make_int2(ec[i], __float_as_int(ew[i]));
    }
}

// ---------------- operand prep -------------------------------------------------
__global__ void asplit_kernel(const float* __restrict__ x, int total2) {
    int i = blockIdx.x * blockDim.x + threadIdx.x;
    if (i < total2) {
        float2 v = reinterpret_cast<const float2*>(x)[i];
        __half hx = __float2half_rn(v.x), hy = __float2half_rn(v.y);
        g_Ah[i] = __halves2half2(hx, hy);
        g_Al[i] = __halves2half2(__float2half_rn(v.x - __half2float(hx)),
                                 __float2half_rn(v.y - __half2float(hy)));
    }
}

__global__ void bprep2_kernel(const float* __restrict__ W) {
    int idx = blockIdx.x * blockDim.x + threadIdx.x;   // 0..32767
    int n  = idx >> 7;
    int k2 = (idx & 127) * 2;
    float w0 = __ldg(&W[(size_t)k2 * 256 + n]);
    float w1 = __ldg(&W[(size_t)(k2 + 1) * 256 + n]);
    __half h0 = __float2half_rn(w0), h1 = __float2half_rn(w1);
    g_Bh2[n * 128 + (k2 >> 1)] = __halves2half2(h0, h1);
    g_Bl2[n * 128 + (k2 >> 1)] =
        __halves2half2(__float2half_rn(w0 - __half2float(h0)),
                       __float2half_rn(w1 - __half2float(h1)));
}

// ---------------- mma.sync GEMM (unchanged, known-good) -----------------------
__device__ __forceinline__ void mma16816(float* c, const uint32_t* a,
                                         uint32_t b0, uint32_t b1) {
    asm volatile(
        "mma.sync.aligned.m16n8k16.row.col.f32.f16.f16.f32 "
        "{%0,%1,%2,%3}, {%4,%5,%6,%7}, {%8,%9}, {%0,%1,%2,%3};"
        : "+f"(c[0]), "+f"(c[1]), "+f"(c[2]), "+f"(c[3])
        : "r"(a[0]), "r"(a[1]), "r"(a[2]), "r"(a[3]), "r"(b0), "r"(b1));
}

#define SMEM_PITCH 20   // halves per row (40 bytes): conflict-free

__global__ __launch_bounds__(128, 2)
void gemm_mma_kernel(const __half* __restrict__ Ah, const __half* __restrict__ Al,
                     const __half* __restrict__ Bh, const __half* __restrict__ Bl,
                     float* __restrict__ C, __half2* __restrict__ Ch, int M) {
    __shared__ __half sAh[128 * SMEM_PITCH];
    __shared__ __half sAl[128 * SMEM_PITCH];
    __shared__ __half sBh[128 * SMEM_PITCH];
    __shared__ __half sBl[128 * SMEM_PITCH];

    int tid  = threadIdx.x;
    int lane = tid & 31;
    int warp = tid >> 5;
    int g    = lane >> 2;
    int tig  = lane & 3;
    int warpM = (warp >> 1) * 64;
    int warpN = (warp & 1) * 64;
    int rowBase = blockIdx.y * 128;
    int colBase = blockIdx.x * 128;

    float acc[4][8][4];
#pragma unroll
    for (int i = 0; i < 4; i++)
#pragma unroll
        for (int j = 0; j < 8; j++)
#pragma unroll
            for (int q = 0; q < 4; q++) acc[i][j][q] = 0.f;

    int aRow = rowBase + tid;
    bool aOk = (aRow < M);
    const uint4* gAh = reinterpret_cast<const uint4*>(Ah + (size_t)aRow * 256);
    const uint4* gAl = reinterpret_cast<const uint4*>(Al + (size_t)aRow * 256);
    const uint4* gBh = reinterpret_cast<const uint4*>(Bh + (size_t)(colBase + tid) * 256);
    const uint4* gBl = reinterpret_cast<const uint4*>(Bl + (size_t)(colBase + tid) * 256);

    uint4 rh0, rh1, rl0, rl1, sh0, sh1, sl0, sl1;
    const uint4 Z = make_uint4(0, 0, 0, 0);

    rh0 = aOk ? __ldg(&gAh[0]) : Z;  rh1 = aOk ? __ldg(&gAh[1]) : Z;
    rl0 = aOk ? __ldg(&gAl[0]) : Z;  rl1 = aOk ? __ldg(&gAl[1]) : Z;
    sh0 = __ldg(&gBh[0]);            sh1 = __ldg(&gBh[1]);
    sl0 = __ldg(&gBl[0]);            sl1 = __ldg(&gBl[1]);

    for (int ks = 0; ks < 16; ks++) {
        __syncthreads();
        {
            uint2* dA = reinterpret_cast<uint2*>(&sAh[tid * SMEM_PITCH]);
            dA[0] = make_uint2(rh0.x, rh0.y); dA[1] = make_uint2(rh0.z, rh0.w);
            dA[2] = make_uint2(rh1.x, rh1.y); dA[3] = make_uint2(rh1.z, rh1.w);
            uint2* dAl = reinterpret_cast<uint2*>(&sAl[tid * SMEM_PITCH]);
            dAl[0] = make_uint2(rl0.x, rl0.y); dAl[1] = make_uint2(rl0.z, rl0.w);
            dAl[2] = make_uint2(rl1.x, rl1.y); dAl[3] = make_uint2(rl1.z, rl1.w);
            uint2* dB = reinterpret_cast<uint2*>(&sBh[tid * SMEM_PITCH]);
            dB[0] = make_uint2(sh0.x, sh0.y); dB[1] = make_uint2(sh0.z, sh0.w);
            dB[2] = make_uint2(sh1.x, sh1.y); dB[3] = make_uint2(sh1.z, sh1.w);
            uint2* dBl = reinterpret_cast<uint2*>(&sBl[tid * SMEM_PITCH]);
            dBl[0] = make_uint2(sl0.x, sl0.y); dBl[1] = make_uint2(sl0.z, sl0.w);
            dBl[2] = make_uint2(sl1.x, sl1.y); dBl[3] = make_uint2(sl1.z, sl1.w);
        }
        __syncthreads();
        if (ks < 15) {
            int o = (ks + 1) * 2;
            rh0 = aOk ? __ldg(&gAh[o]) : Z;  rh1 = aOk ? __ldg(&gAh[o + 1]) : Z;
            rl0 = aOk ? __ldg(&gAl[o]) : Z;  rl1 = aOk ? __ldg(&gAl[o + 1]) : Z;
            sh0 = __ldg(&gBh[o]);            sh1 = __ldg(&gBh[o + 1]);
            sl0 = __ldg(&gBl[o]);            sl1 = __ldg(&gBl[o + 1]);
        }

        uint32_t ah[4][4], al[4][4];
#pragma unroll
        for (int mi = 0; mi < 4; mi++) {
            int r = warpM + mi * 16 + g;
            ah[mi][0] = *reinterpret_cast<const uint32_t*>(&sAh[r * SMEM_PITCH + 2 * tig]);
            ah[mi][1] = *reinterpret_cast<const uint32_t*>(&sAh[(r + 8) * SMEM_PITCH + 2 * tig]);
            ah[mi][2] = *reinterpret_cast<const uint32_t*>(&sAh[r * SMEM_PITCH + 2 * tig + 8]);
            ah[mi][3] = *reinterpret_cast<const uint32_t*>(&sAh[(r + 8) * SMEM_PITCH + 2 * tig + 8]);
            al[mi][0] = *reinterpret_cast<const uint32_t*>(&sAl[r * SMEM_PITCH + 2 * tig]);
            al[mi][1] = *reinterpret_cast<const uint32_t*>(&sAl[(r + 8) * SMEM_PITCH + 2 * tig]);
            al[mi][2] = *reinterpret_cast<const uint32_t*>(&sAl[r * SMEM_PITCH + 2 * tig + 8]);
            al[mi][3] = *reinterpret_cast<const uint32_t*>(&sAl[(r + 8) * SMEM_PITCH + 2 * tig + 8]);
        }
#pragma unroll
        for (int ni = 0; ni < 8; ni++) {
            int n = warpN + ni * 8 + g;
            uint32_t bh0 = *reinterpret_cast<const uint32_t*>(&sBh[n * SMEM_PITCH + 2 * tig]);
            uint32_t bh1 = *reinterpret_cast<const uint32_t*>(&sBh[n * SMEM_PITCH + 2 * tig + 8]);
            uint32_t bl0 = *reinterpret_cast<const uint32_t*>(&sBl[n * SMEM_PITCH + 2 * tig]);
            uint32_t bl1 = *reinterpret_cast<const uint32_t*>(&sBl[n * SMEM_PITCH + 2 * tig + 8]);
#pragma unroll
            for (int mi = 0; mi < 4; mi++) {
                mma16816(acc[mi][ni], ah[mi], bh0, bh1);
                mma16816(acc[mi][ni], al[mi], bh0, bh1);
                mma16816(acc[mi][ni], ah[mi], bl0, bl1);
            }
        }
    }

#pragma unroll
    for (int mi = 0; mi < 4; mi++) {
#pragma unroll
        for (int ni = 0; ni < 8; ni++) {
            int row0 = rowBase + warpM + mi * 16 + g;
            int col  = colBase + warpN + ni * 8 + 2 * tig;
            float* a = acc[mi][ni];
            if (row0 < M) {
                *reinterpret_cast<float2*>(&C[(size_t)row0 * 256 + col]) = make_float2(a[0], a[1]);
                Ch[(size_t)row0 * 128 + (col >> 1)] = __floats2half2_rn(a[0], a[1]);
            }
            int row1 = row0 + 8;
            if (row1 < M) {
                *reinterpret_cast<float2*>(&C[(size_t)row1 * 256 + col]) = make_float2(a[2], a[3]);
                Ch[(size_t)row1 * 128 + (col >> 1)] = __floats2half2_rn(a[2], a[3]);
            }
        }
    }
}

// ---------------- SpMM helpers -------------------------------------------------
// int8 byte pair -> half2 of signed counts: m = 0x6400|b  (=1024+b), then
// m - 1152 = (q+128) - 128 = q exactly (all integers <= 2048 exact in fp16).
__device__ __forceinline__ __half2 dequant_pair(uint32_t u) {
    uint32_t mm;
    asm("prmt.b32 %0, %1, %2, 0x5150;" : "=r"(mm) : "r"(u), "r"(0x64006400u));
    __half2 m2 = *reinterpret_cast<__half2*>(&mm);
    const __half2 c1152 = __half2half2(__float2half_rn(1152.f));
    return __hsub2(m2, c1152);
}

// block-reduce max over 128 threads; returns row max to all threads
__device__ __forceinline__ float block_max128(float v, float* smax) {
#pragma unroll
    for (int off = 16; off > 0; off >>= 1)
        v = fmaxf(v, __shfl_xor_sync(0xFFFFFFFFu, v, off));
    int warp = threadIdx.x >> 5;
    if ((threadIdx.x & 31) == 0) smax[warp] = v;
    __syncthreads();
    return fmaxf(fmaxf(smax[0], smax[1]), fmaxf(smax[2], smax[3]));
}

// ---------------- hop 1: fp16 gather -> fp16 + int8 outputs -------------------
__global__ __launch_bounds__(128)
void spmm_h1_kernel(const __half2* __restrict__ in, __half2* __restrict__ outh,
                    unsigned char* __restrict__ outq, float* __restrict__ outs) {
    int row = blockIdx.x;
    int d = threadIdx.x;
    int beg = __ldg(&g_row_ptr[row]);
    int end = __ldg(&g_row_ptr[row + 1]);

    __shared__ int2 se[128];
    __shared__ float smax[4];

    float accx = 0.f, accy = 0.f;
    for (int base = beg; base < end; base += 128) {
        int m = end - base; if (m > 128) m = 128;
        __syncthreads();
        if (d < m) {
            int2 e = __ldg(&g_csr[base + d]);
            uint32_t wb = (uint32_t)__half_as_ushort(__float2half_rn(__int_as_float(e.y)));
            se[d] = make_int2(e.x, (int)(wb * 0x00010001u));
        }
        __syncthreads();
        int j = 0;
        for (; j + 8 <= m; j += 8) {
            __half2 hacc = __half2half2(__ushort_as_half(0));
#pragma unroll
            for (int t = 0; t < 8; t++) {
                int2 e = se[j + t];
                __half2 v = __ldg(in + (size_t)e.x * 128 + d);
                __half2 w2 = *reinterpret_cast<__half2*>(&e.y);
                hacc = __hfma2(w2, v, hacc);
            }
            float2 f = __half22float2(hacc);
            accx += f.x; accy += f.y;
        }
        if (j < m) {
            __half2 hacc = __half2half2(__ushort_as_half(0));
            for (; j < m; j++) {
                int2 e = se[j];
                __half2 v = __ldg(in + (size_t)e.x * 128 + d);
                __half2 w2 = *reinterpret_cast<__half2*>(&e.y);
                hacc = __hfma2(w2, v, hacc);
            }
            float2 f = __half22float2(hacc);
            accx += f.x; accy += f.y;
        }
    }

    size_t o = (size_t)row * 128 + d;
    outh[o] = __floats2half2_rn(accx, accy);

    __syncthreads();
    float rm = block_max128(fmaxf(fabsf(accx), fabsf(accy)), smax);
    float inv = (rm > 0.f) ? (127.f / rm) : 0.f;
    if (d == 0) outs[row] = (rm > 0.f) ? (rm / 127.f) : 0.f;
    int qx = __float2int_rn(accx * inv) + 128;
    int qy = __float2int_rn(accy * inv) + 128;
    reinterpret_cast<unsigned short*>(outq)[o] =
        (unsigned short)((qx & 0xFF) | ((qy & 0xFF) << 8));
}

// ---------------- hop 2: int8 gather -> fp16 + int8 outputs -------------------
__global__ __launch_bounds__(128)
void spmm_q_kernel(const unsigned char* __restrict__ inq, const float* __restrict__ ins,
                   __half2* __restrict__ outh, unsigned char* __restrict__ outq,
                   float* __restrict__ outs) {
    int row = blockIdx.x;
    int d = threadIdx.x;
    int beg = __ldg(&g_row_ptr[row]);
    int end = __ldg(&g_row_ptr[row + 1]);

    __shared__ int2 se[128];
    __shared__ float smax[4];

    float accx = 0.f, accy = 0.f;
    for (int base = beg; base < end; base += 128) {
        int m = end - base; if (m > 128) m = 128;
        __syncthreads();
        if (d < m) {
            int2 e = __ldg(&g_csr[base + d]);
            float wp = __int_as_float(e.y) * __ldg(&ins[e.x]) * 64.f;   // scale*64 fold
            uint32_t wb = (uint32_t)__half_as_ushort(__float2half_rn(wp));
            se[d] = make_int2(e.x, (int)(wb * 0x00010001u));
        }
        __syncthreads();
        int j = 0;
        for (; j + 8 <= m; j += 8) {
            __half2 hacc = __half2half2(__ushort_as_half(0));
#pragma unroll
            for (int t = 0; t < 8; t++) {
                int2 e = se[j + t];
                uint32_t u = (uint32_t)__ldg(reinterpret_cast<const unsigned short*>(
                                 inq + (size_t)e.x * 256) + d);
                __half2 w2 = *reinterpret_cast<__half2*>(&e.y);
                hacc = __hfma2(w2, dequant_pair(u), hacc);
            }
            float2 f = __half22float2(hacc);
            accx += f.x; accy += f.y;
        }
        if (j < m) {
            __half2 hacc = __half2half2(__ushort_as_half(0));
            for (; j < m; j++) {
                int2 e = se[j];
                uint32_t u = (uint32_t)__ldg(reinterpret_cast<const unsigned short*>(
                                 inq + (size_t)e.x * 256) + d);
                __half2 w2 = *reinterpret_cast<__half2*>(&e.y);
                hacc = __hfma2(w2, dequant_pair(u), hacc);
            }
            float2 f = __half22float2(hacc);
            accx += f.x; accy += f.y;
        }
    }
    accx *= 0.015625f;   // undo *64 fold
    accy *= 0.015625f;

    size_t o = (size_t)row * 128 + d;
    outh[o] = __floats2half2_rn(accx, accy);

    __syncthreads();
    float rm = block_max128(fmaxf(fabsf(accx), fabsf(accy)), smax);
    float inv = (rm > 0.f) ? (127.f / rm) : 0.f;
    if (d == 0) outs[row] = (rm > 0.f) ? (rm / 127.f) : 0.f;
    int qx = __float2int_rn(accx * inv) + 128;
    int qy = __float2int_rn(accy * inv) + 128;
    reinterpret_cast<unsigned short*>(outq)[o] =
        (unsigned short)((qx & 0xFF) | ((qy & 0xFF) << 8));
}

// ---------------- hop 3 (fused final): out += h1 + h2 + h3 + bias -------------
__global__ __launch_bounds__(128)
void spmm_q_final_kernel(const unsigned char* __restrict__ inq,
                         const float* __restrict__ ins,
                         const __half2* __restrict__ h1, const __half2* __restrict__ h2,
                         float* __restrict__ out, const float* __restrict__ bias) {
    int row = blockIdx.x;
    int d = threadIdx.x;
    int beg = __ldg(&g_row_ptr[row]);
    int end = __ldg(&g_row_ptr[row + 1]);

    __shared__ int2 se[128];

    float accx = 0.f, accy = 0.f;
    for (int base = beg; base < end; base += 128) {
        int m = end - base; if (m > 128) m = 128;
        __syncthreads();
        if (d < m) {
            int2 e = __ldg(&g_csr[base + d]);
            float wp = __int_as_float(e.y) * __ldg(&ins[e.x]) * 64.f;
            uint32_t wb = (uint32_t)__half_as_ushort(__float2half_rn(wp));
            se[d] = make_int2(e.x, (int)(wb * 0x00010001u));
        }
        __syncthreads();
        int j = 0;
        for (; j + 8 <= m; j += 8) {
            __half2 hacc = __half2half2(__ushort_as_half(0));
#pragma unroll
            for (int t = 0; t < 8; t++) {
                int2 e = se[j + t];
                uint32_t u = (uint32_t)__ldg(reinterpret_cast<const unsigned short*>(
                                 inq + (size_t)e.x * 256) + d);
                __half2 w2 = *reinterpret_cast<__half2*>(&e.y);
                hacc = __hfma2(w2, dequant_pair(u), hacc);
            }
            float2 f = __half22float2(hacc);
            accx += f.x; accy += f.y;
        }
        if (j < m) {
            __half2 hacc = __half2half2(__ushort_as_half(0));
            for (; j < m; j++) {
                int2 e = se[j];
                uint32_t u = (uint32_t)__ldg(reinterpret_cast<const unsigned short*>(
                                 inq + (size_t)e.x * 256) + d);
                __half2 w2 = *reinterpret_cast<__half2*>(&e.y);
                hacc = __hfma2(w2, dequant_pair(u), hacc);
            }
            float2 f = __half22float2(hacc);
            accx += f.x; accy += f.y;
        }
    }
    accx *= 0.015625f;
    accy *= 0.015625f;

    size_t o = (size_t)row * 128 + d;
    float2 a = reinterpret_cast<float2*>(out)[o];
    float2 f1 = __half22float2(h1[o]);
    float2 f2 = __half22float2(h2[o]);
    a.x += f1.x + f2.x + accx + __ldg(bias + 2 * d);
    a.y += f1.y + f2.y + accy + __ldg(bias + 2 * d + 1);
    reinterpret_cast<float2*>(out)[o] = a;
}

// ---------------- launch ------------------------------------------------------
extern "C" void kernel_launch(void* const* d_in, const int* in_sizes, int n_in,
                              void* d_out, int out_size) {
    const float* x    = (const float*)d_in[0];
    const float* w    = (const float*)d_in[1];
    const float* bias = (const float*)d_in[2];
    const float* ew   = (const float*)d_in[3];
    const int*   er   = (const int*)d_in[4];
    const int*   ec   = (const int*)d_in[5];
    float* out = (float*)d_out;

    const int N = in_sizes[0] / DD;   // 100000
    const int E = in_sizes[3];        // 3200000

    void *pa, *pb, *pc, *pq1, *pq2, *ps1, *ps2, *pah, *pal, *pbh, *pbl;
    cudaGetSymbolAddress(&pa,  g_hbuf_a);
    cudaGetSymbolAddress(&pb,  g_hbuf_b);
    cudaGetSymbolAddress(&pc,  g_hbuf_c);
    cudaGetSymbolAddress(&pq1, g_q1);
    cudaGetSymbolAddress(&pq2, g_q2);
    cudaGetSymbolAddress(&ps1, g_s1);
    cudaGetSymbolAddress(&ps2, g_s2);
    cudaGetSymbolAddress(&pah, g_Ah);
    cudaGetSymbolAddress(&pal, g_Al);
    cudaGetSymbolAddress(&pbh, g_Bh2);
    cudaGetSymbolAddress(&pbl, g_Bl2);

    // 1) CSR build + operand prep
    zero_counts_kernel<<<(N + 256) / 256, 256>>>(N + 1);
    hist_kernel<<<(E + 255) / 256, 256>>>(er, E);
    scan_kernel<<<1, 1024>>>(N, E);
    scatter_kernel<<<(E + 255) / 256, 256>>>(er, ec, ew, E);
    asplit_kernel<<<(N * 128 + 255) / 256, 256>>>(x, N * 128);
    bprep2_kernel<<<128, 256>>>(w);

    // 2) support = x @ W  -> d_out (fp32) and hbuf_a (fp16 gather buf)
    dim3 ggrid(2, (N + 127) / 128);
    gemm_mma_kernel<<<ggrid, 128>>>((const __half*)pah, (const __half*)pal,
                                    (const __half*)pbh, (const __half*)pbl,
                                    out, (__half2*)pa, N);

    // 3) hops: h1 (fp16 gather), h2/h3 (int8 gather); final add fused into hop 3
    spmm_h1_kernel<<<N, 128>>>((const __half2*)pa, (__half2*)pb,
                               (unsigned char*)pq1, (float*)ps1);
    spmm_q_kernel<<<N, 128>>>((const unsigned char*)pq1, (const float*)ps1,
                              (__half2*)pc, (unsigned char*)pq2, (float*)ps2);
    spmm_q_final_kernel<<<N, 128>>>((const unsigned char*)pq2, (const float*)ps2,
                                    (const __half2*)pb, (const __half2*)pc,
                                    out, bias);
}